// round 1
// baseline (speedup 1.0000x reference)
#include <cuda_runtime.h>
#include <math.h>

#define NN    50000
#define EE    800000
#define ETOTE 850000
#define BB    64
#define FIN   128
#define POSD  16
#define ENHD  144
#define HH    4
#define CCD   64
#define HCC   256
#define OUTD  128
#define BNEPS 1e-5f

// ---------------- scratch (static device globals; no allocation) ----------------
__device__ float  g_h0[NN * ENHD];      // concat(x, pe)            28.8 MB
__device__ float  g_hl[NN * HCC];       // linear output h = A @ W  51.2 MB
__device__ float  g_hagg[NN * HCC];     // GAT aggregate / BN out   51.2 MB
__device__ float  g_as[NN * HH];
__device__ float  g_ad[NN * HH];
__device__ int    g_counts[BB];
__device__ int    g_starts[BB];
__device__ int    g_gridsz[BB];
__device__ float  g_denomv[BB];
__device__ int    g_indeg[NN];
__device__ int    g_rowstart[NN + 1];
__device__ int    g_fillpos[NN];
__device__ int    g_csrsrc[ETOTE];
__device__ int    g_bsum[256];
__device__ double g_sum[HCC];
__device__ double g_sumsq[HCC];
__device__ float  g_mean[HCC];
__device__ float  g_rstd[HCC];
__device__ float  g_pooled[BB * HCC];

// ---------------- graph meta ----------------
__global__ void k_prep_zero() {
    int i = blockIdx.x * blockDim.x + threadIdx.x;
    if (i < NN) g_indeg[i] = 0;
    if (i < BB) g_counts[i] = 0;
}

__global__ void k_count_nodes(const int* __restrict__ batch) {
    int i = blockIdx.x * blockDim.x + threadIdx.x;
    if (i < NN) atomicAdd(&g_counts[batch[i]], 1);
}

__global__ void k_graph_meta() {
    int b = threadIdx.x;
    if (b >= BB) return;
    int st = 0;
    for (int j = 0; j < b; j++) st += g_counts[j];
    g_starts[b] = st;
    int c = g_counts[b];
    int g = (int)ceil(sqrt((double)c));
    g_gridsz[b] = g;
    int d = g - 1; if (d < 1) d = 1;
    g_denomv[b] = (float)d;
}

// h0 = concat(x, pos @ W_pos + b_pos)
__global__ void k_build_h0(const float* __restrict__ x, const int* __restrict__ batch,
                           const float* __restrict__ Wpos, const float* __restrict__ bpos) {
    int n = blockIdx.x;
    int t = threadIdx.x;
    if (t < FIN) {
        g_h0[(size_t)n * ENHD + t] = x[(size_t)n * FIN + t];
    } else if (t < ENHD) {
        int b = batch[n];
        int i = n - g_starts[b];
        int g = g_gridsz[b];
        float denom = g_denomv[b];
        int row = i / g;
        int col = i - row * g;
        float p0 = (float)row / denom;
        float p1 = (float)col / denom;
        int j = t - FIN;
        g_h0[(size_t)n * ENHD + t] = p0 * Wpos[j] + p1 * Wpos[POSD + j] + bpos[j];
    }
}

// ---------------- CSR by destination (edges + self loops) ----------------
__global__ void k_edge_count(const int* __restrict__ ei) {
    int e = blockIdx.x * blockDim.x + threadIdx.x;
    if (e >= ETOTE) return;
    int dst = (e < EE) ? ei[EE + e] : (e - EE);
    atomicAdd(&g_indeg[dst], 1);
}

__global__ void k_scanA() {   // per-block exclusive scan + block sums
    __shared__ int s[256];
    int i = blockIdx.x * 256 + threadIdx.x;
    int v = (i < NN) ? g_indeg[i] : 0;
    s[threadIdx.x] = v;
    __syncthreads();
    for (int off = 1; off < 256; off <<= 1) {
        int t = (threadIdx.x >= off) ? s[threadIdx.x - off] : 0;
        __syncthreads();
        s[threadIdx.x] += t;
        __syncthreads();
    }
    if (i < NN) g_rowstart[i] = s[threadIdx.x] - v;     // exclusive within block
    if (threadIdx.x == 255) g_bsum[blockIdx.x] = s[255];
}

__global__ void k_scanB() {   // 1 block: exclusive scan of 196 block sums
    __shared__ int s[256];
    int t = threadIdx.x;
    int v = (t < 196) ? g_bsum[t] : 0;
    s[t] = v;
    __syncthreads();
    for (int off = 1; off < 256; off <<= 1) {
        int u = (t >= off) ? s[t - off] : 0;
        __syncthreads();
        s[t] += u;
        __syncthreads();
    }
    if (t < 196) g_bsum[t] = s[t] - v;
}

__global__ void k_scanC() {
    int i = blockIdx.x * 256 + threadIdx.x;
    if (i < NN) g_rowstart[i] += g_bsum[blockIdx.x];
    if (i == 0) g_rowstart[NN] = ETOTE;
}

__global__ void k_fill_init() {
    int i = blockIdx.x * blockDim.x + threadIdx.x;
    if (i < NN) g_fillpos[i] = g_rowstart[i];
}

__global__ void k_edge_fill(const int* __restrict__ ei) {
    int e = blockIdx.x * blockDim.x + threadIdx.x;
    if (e >= ETOTE) return;
    int src, dst;
    if (e < EE) { src = ei[e]; dst = ei[EE + e]; }
    else        { src = e - EE; dst = src; }
    int p = atomicAdd(&g_fillpos[dst], 1);
    g_csrsrc[p] = src;
}

// ---------------- tiled SIMT fp32 GEMM: C[M,256] = A[M,K] @ W[K,256] ----------------
// sel: 0 -> A = g_h0 (K=144), 1 -> A = g_hagg (K=256). C = g_hl.
__global__ void k_gemm(const float* __restrict__ Wm, int sel, int K) {
    const float* __restrict__ A = (sel == 0) ? g_h0 : g_hagg;
    float* __restrict__ Co = g_hl;
    const int M = NN, Nc = HCC;
    __shared__ float As[16][64];
    __shared__ float Bs[16][64];
    int tid = threadIdx.x;              // 256
    int m0 = blockIdx.x * 64;
    int n0 = blockIdx.y * 64;
    int tx = tid & 15, ty = tid >> 4;
    float acc[4][4];
    #pragma unroll
    for (int i = 0; i < 4; i++)
        #pragma unroll
        for (int j = 0; j < 4; j++) acc[i][j] = 0.f;

    for (int k0 = 0; k0 < K; k0 += 16) {
        {   // A tile 64x16, transposed into As[k][m]
            int idx = tid * 4;
            int r = idx >> 4;
            int kk = idx & 15;
            int gr = m0 + r;
            float4 v = make_float4(0.f, 0.f, 0.f, 0.f);
            if (gr < M) v = *(const float4*)(A + (size_t)gr * K + k0 + kk);
            As[kk + 0][r] = v.x; As[kk + 1][r] = v.y;
            As[kk + 2][r] = v.z; As[kk + 3][r] = v.w;
        }
        {   // W tile 16x64
            int idx = tid * 4;
            int kk = idx >> 6;
            int n = idx & 63;
            float4 v = *(const float4*)(Wm + (size_t)(k0 + kk) * Nc + n0 + n);
            *(float4*)&Bs[kk][n] = v;
        }
        __syncthreads();
        #pragma unroll
        for (int kk = 0; kk < 16; kk++) {
            float a[4], b[4];
            #pragma unroll
            for (int i = 0; i < 4; i++) a[i] = As[kk][ty * 4 + i];
            #pragma unroll
            for (int j = 0; j < 4; j++) b[j] = Bs[kk][tx * 4 + j];
            #pragma unroll
            for (int i = 0; i < 4; i++)
                #pragma unroll
                for (int j = 0; j < 4; j++) acc[i][j] += a[i] * b[j];
        }
        __syncthreads();
    }
    #pragma unroll
    for (int i = 0; i < 4; i++) {
        int gr = m0 + ty * 4 + i;
        if (gr < M) {
            float4 v = make_float4(acc[i][0], acc[i][1], acc[i][2], acc[i][3]);
            *(float4*)(Co + (size_t)gr * Nc + n0 + tx * 4) = v;
        }
    }
}

// ---------------- per-node attention logits: alpha_s, alpha_d ----------------
// one warp per (node, head)
__global__ void k_alpha(const float* __restrict__ asrc, const float* __restrict__ adst) {
    int gid = blockIdx.x * blockDim.x + threadIdx.x;
    int warp = gid >> 5;
    int lane = gid & 31;
    if (warp >= NN * HH) return;
    int n = warp >> 2;
    int h = warp & 3;
    const float* row = g_hl + (size_t)n * HCC + h * CCD;
    float v0 = row[lane], v1 = row[lane + 32];
    float s1 = v0 * asrc[h * CCD + lane] + v1 * asrc[h * CCD + lane + 32];
    float s2 = v0 * adst[h * CCD + lane] + v1 * adst[h * CCD + lane + 32];
    #pragma unroll
    for (int off = 16; off; off >>= 1) {
        s1 += __shfl_down_sync(0xFFFFFFFFu, s1, off);
        s2 += __shfl_down_sync(0xFFFFFFFFu, s2, off);
    }
    if (lane == 0) {
        g_as[n * HH + h] = s1;
        g_ad[n * HH + h] = s2;
    }
}

// ---------------- GAT gather: one warp per destination node ----------------
// softmax over incoming edges per head + weighted sum of h[src]; no atomics.
__global__ void k_gat_gather() {
    int gid = blockIdx.x * blockDim.x + threadIdx.x;
    int dst = gid >> 5;
    int lane = gid & 31;
    if (dst >= NN) return;
    int h = lane >> 3;                  // 8 lanes per head
    float adh = g_ad[dst * HH + h];
    int beg = g_rowstart[dst], end = g_rowstart[dst + 1];

    // pass 1: max
    float mx = -1e30f;
    for (int e = beg; e < end; e++) {
        int s = g_csrsrc[e];
        float v = g_as[s * HH + h] + adh;
        v = (v > 0.f) ? v : 0.2f * v;
        mx = fmaxf(mx, v);
    }
    // pass 2: sum of exp
    float sum = 0.f;
    for (int e = beg; e < end; e++) {
        int s = g_csrsrc[e];
        float v = g_as[s * HH + h] + adh;
        v = (v > 0.f) ? v : 0.2f * v;
        sum += expf(v - mx);
    }
    float rs = 1.f / sum;
    // pass 3: weighted accumulate (8 channels per lane)
    float acc[8];
    #pragma unroll
    for (int k = 0; k < 8; k++) acc[k] = 0.f;
    for (int e = beg; e < end; e++) {
        int s = g_csrsrc[e];
        float v = g_as[s * HH + h] + adh;
        v = (v > 0.f) ? v : 0.2f * v;
        float a = expf(v - mx) * rs;
        const float4* hp = (const float4*)(g_hl + (size_t)s * HCC + lane * 8);
        float4 p0 = hp[0], p1 = hp[1];
        acc[0] += a * p0.x; acc[1] += a * p0.y; acc[2] += a * p0.z; acc[3] += a * p0.w;
        acc[4] += a * p1.x; acc[5] += a * p1.y; acc[6] += a * p1.z; acc[7] += a * p1.w;
    }
    float4* op = (float4*)(g_hagg + (size_t)dst * HCC + lane * 8);
    op[0] = make_float4(acc[0], acc[1], acc[2], acc[3]);
    op[1] = make_float4(acc[4], acc[5], acc[6], acc[7]);
}

// ---------------- BatchNorm (over nodes) + ELU ----------------
__global__ void k_bn_zero() {
    int c = threadIdx.x;
    g_sum[c] = 0.0;
    g_sumsq[c] = 0.0;
}

__global__ void k_bn_stats() {      // 250 blocks x 200 rows, 256 threads (one per channel)
    int c = threadIdx.x;
    int r0 = blockIdx.x * 200;
    float s = 0.f, sq = 0.f;
    for (int r = r0; r < r0 + 200; r++) {
        float v = g_hagg[(size_t)r * HCC + c];
        s += v;
        sq += v * v;
    }
    atomicAdd(&g_sum[c], (double)s);
    atomicAdd(&g_sumsq[c], (double)sq);
}

__global__ void k_bn_final() {
    int c = threadIdx.x;
    double m = g_sum[c] / (double)NN;
    double var = g_sumsq[c] / (double)NN - m * m;
    g_mean[c] = (float)m;
    g_rstd[c] = (float)(1.0 / sqrt(var + (double)BNEPS));
}

__global__ void k_bn_apply_elu(const float* __restrict__ gamma, const float* __restrict__ beta) {
    int idx = blockIdx.x * blockDim.x + threadIdx.x;   // over N*HC/4
    if (idx >= NN * HCC / 4) return;
    int c0 = (idx * 4) & (HCC - 1);
    float4 v = ((float4*)g_hagg)[idx];
    float y;
    y = gamma[c0 + 0] * (v.x - g_mean[c0 + 0]) * g_rstd[c0 + 0] + beta[c0 + 0];
    v.x = (y > 0.f) ? y : expm1f(y);
    y = gamma[c0 + 1] * (v.y - g_mean[c0 + 1]) * g_rstd[c0 + 1] + beta[c0 + 1];
    v.y = (y > 0.f) ? y : expm1f(y);
    y = gamma[c0 + 2] * (v.z - g_mean[c0 + 2]) * g_rstd[c0 + 2] + beta[c0 + 2];
    v.z = (y > 0.f) ? y : expm1f(y);
    y = gamma[c0 + 3] * (v.w - g_mean[c0 + 3]) * g_rstd[c0 + 3] + beta[c0 + 3];
    v.w = (y > 0.f) ? y : expm1f(y);
    ((float4*)g_hagg)[idx] = v;
}

// ---------------- pooling + FC ----------------
__global__ void k_pool() {          // one block per graph, thread = channel
    int b = blockIdx.x;
    int c = threadIdx.x;
    int st = g_starts[b], cnt = g_counts[b];
    float s = 0.f;
    for (int r = st; r < st + cnt; r++) s += g_hagg[(size_t)r * HCC + c];
    g_pooled[b * HCC + c] = s / (float)cnt;
}

__global__ void k_fc(const float* __restrict__ Wfc, const float* __restrict__ bfc,
                     float* __restrict__ out) {
    int b = blockIdx.x;
    int j = threadIdx.x;
    float s = bfc[j];
    #pragma unroll 4
    for (int k = 0; k < HCC; k++) s += g_pooled[b * HCC + k] * Wfc[k * OUTD + j];
    out[b * OUTD + j] = s;
}

// ---------------- launch ----------------
extern "C" void kernel_launch(void* const* d_in, const int* in_sizes, int n_in,
                              void* d_out, int out_size) {
    const float* x      = (const float*)d_in[0];
    const int*   ei     = (const int*)d_in[1];
    const int*   batch  = (const int*)d_in[2];
    const float* Wpos   = (const float*)d_in[3];
    const float* bpos   = (const float*)d_in[4];
    const float* W1     = (const float*)d_in[5];
    const float* asrc1  = (const float*)d_in[6];
    const float* adst1  = (const float*)d_in[7];
    // d_in[8] = b1 (cancels exactly inside BatchNorm)
    const float* gamma1 = (const float*)d_in[9];
    const float* beta1  = (const float*)d_in[10];
    const float* W2     = (const float*)d_in[11];
    const float* asrc2  = (const float*)d_in[12];
    const float* adst2  = (const float*)d_in[13];
    // d_in[14] = b2 (cancels)
    const float* gamma2 = (const float*)d_in[15];
    const float* beta2  = (const float*)d_in[16];
    const float* Wfc    = (const float*)d_in[17];
    const float* bfc    = (const float*)d_in[18];
    float* out = (float*)d_out;

    const int NB = (NN + 255) / 256;          // 196
    const int EB = (ETOTE + 255) / 256;       // 3321

    // graph metadata + positions + h0
    k_prep_zero<<<NB, 256>>>();
    k_count_nodes<<<NB, 256>>>(batch);
    k_graph_meta<<<1, 64>>>();
    k_build_h0<<<NN, 160>>>(x, batch, Wpos, bpos);

    // CSR by dst (shared by both layers)
    k_edge_count<<<EB, 256>>>(ei);
    k_scanA<<<NB, 256>>>();
    k_scanB<<<1, 256>>>();
    k_scanC<<<NB, 256>>>();
    k_fill_init<<<NB, 256>>>();
    k_edge_fill<<<EB, 256>>>(ei);

    dim3 ggrid((NN + 63) / 64, HCC / 64);

    // ----- layer 1 -----
    k_gemm<<<ggrid, 256>>>(W1, 0, ENHD);
    k_alpha<<<(NN * HH * 32) / 256, 256>>>(asrc1, adst1);
    k_gat_gather<<<(NN * 32) / 256, 256>>>();
    k_bn_zero<<<1, 256>>>();
    k_bn_stats<<<250, 256>>>();
    k_bn_final<<<1, 256>>>();
    k_bn_apply_elu<<<(NN * HCC / 4) / 256, 256>>>(gamma1, beta1);

    // ----- layer 2 -----
    k_gemm<<<ggrid, 256>>>(W2, 1, HCC);
    k_alpha<<<(NN * HH * 32) / 256, 256>>>(asrc2, adst2);
    k_gat_gather<<<(NN * 32) / 256, 256>>>();
    k_bn_zero<<<1, 256>>>();
    k_bn_stats<<<250, 256>>>();
    k_bn_final<<<1, 256>>>();
    k_bn_apply_elu<<<(NN * HCC / 4) / 256, 256>>>(gamma2, beta2);

    // pool + fc
    k_pool<<<BB, 256>>>();
    k_fc<<<BB, 128>>>(Wfc, bfc, out);
}

// round 2
// speedup vs baseline: 1.0622x; 1.0622x over previous
#include <cuda_runtime.h>
#include <math.h>

#define NN    50000
#define EE    800000
#define ETOTE 850000
#define BB    64
#define FIN   128
#define POSD  16
#define ENHD  144
#define HH    4
#define CCD   64
#define HCC   256
#define OUTD  128
#define BNEPS 1e-5f

// ---------------- scratch ----------------
__device__ float  g_h0[NN * ENHD];
__device__ float  g_hl[NN * HCC];
__device__ float  g_hagg[NN * HCC];
__device__ float  g_as[NN * HH];
__device__ float  g_ad[NN * HH];
__device__ int    g_counts[BB];
__device__ int    g_starts[BB];
__device__ int    g_gridsz[BB];
__device__ float  g_denomv[BB];
__device__ int    g_indeg[NN];
__device__ int    g_rowstart[NN + 1];
__device__ int    g_fillpos[NN];
__device__ int    g_csrsrc[ETOTE];
__device__ int    g_bsum[256];
__device__ double g_sum[HCC];
__device__ double g_sumsq[HCC];
__device__ float  g_mean[HCC];
__device__ float  g_rstd[HCC];
__device__ float  g_pooled[BB * HCC];

// ---------------- graph meta ----------------
__global__ void k_prep_zero() {
    int i = blockIdx.x * blockDim.x + threadIdx.x;
    if (i < NN) g_indeg[i] = 0;
    if (i < BB) g_counts[i] = 0;
}

__global__ void k_count_nodes(const int* __restrict__ batch) {
    int i = blockIdx.x * blockDim.x + threadIdx.x;
    if (i < NN) atomicAdd(&g_counts[batch[i]], 1);
}

__global__ void k_graph_meta() {
    int b = threadIdx.x;
    if (b >= BB) return;
    int st = 0;
    for (int j = 0; j < b; j++) st += g_counts[j];
    g_starts[b] = st;
    int c = g_counts[b];
    int g = (int)ceil(sqrt((double)c));
    g_gridsz[b] = g;
    int d = g - 1; if (d < 1) d = 1;
    g_denomv[b] = (float)d;
}

// h0 = concat(x, pos @ W_pos + b_pos); one float4 per thread, coalesced.
__global__ void k_build_h0(const float* __restrict__ x, const int* __restrict__ batch,
                           const float* __restrict__ Wpos, const float* __restrict__ bpos) {
    int tid = blockIdx.x * blockDim.x + threadIdx.x;      // over NN*36 float4s
    if (tid >= NN * (ENHD / 4)) return;
    int n = tid / (ENHD / 4);
    int f4 = tid - n * (ENHD / 4);
    float4 v;
    if (f4 < FIN / 4) {
        v = ((const float4*)x)[(size_t)n * (FIN / 4) + f4];
    } else {
        int b = batch[n];
        int i = n - g_starts[b];
        int g = g_gridsz[b];
        float denom = g_denomv[b];
        int row = i / g;
        int col = i - row * g;
        float p0 = (float)row / denom;
        float p1 = (float)col / denom;
        int j = (f4 - FIN / 4) * 4;
        v.x = p0 * Wpos[j + 0] + p1 * Wpos[POSD + j + 0] + bpos[j + 0];
        v.y = p0 * Wpos[j + 1] + p1 * Wpos[POSD + j + 1] + bpos[j + 1];
        v.z = p0 * Wpos[j + 2] + p1 * Wpos[POSD + j + 2] + bpos[j + 2];
        v.w = p0 * Wpos[j + 3] + p1 * Wpos[POSD + j + 3] + bpos[j + 3];
    }
    ((float4*)g_h0)[tid] = v;
}

// ---------------- CSR by destination ----------------
__global__ void k_edge_count(const int* __restrict__ ei) {
    int e = blockIdx.x * blockDim.x + threadIdx.x;
    if (e >= ETOTE) return;
    int dst = (e < EE) ? ei[EE + e] : (e - EE);
    atomicAdd(&g_indeg[dst], 1);
}

__global__ void k_scanA() {
    __shared__ int s[256];
    int i = blockIdx.x * 256 + threadIdx.x;
    int v = (i < NN) ? g_indeg[i] : 0;
    s[threadIdx.x] = v;
    __syncthreads();
    for (int off = 1; off < 256; off <<= 1) {
        int t = (threadIdx.x >= off) ? s[threadIdx.x - off] : 0;
        __syncthreads();
        s[threadIdx.x] += t;
        __syncthreads();
    }
    if (i < NN) g_rowstart[i] = s[threadIdx.x] - v;
    if (threadIdx.x == 255) g_bsum[blockIdx.x] = s[255];
}

__global__ void k_scanB() {
    __shared__ int s[256];
    int t = threadIdx.x;
    int v = (t < 196) ? g_bsum[t] : 0;
    s[t] = v;
    __syncthreads();
    for (int off = 1; off < 256; off <<= 1) {
        int u = (t >= off) ? s[t - off] : 0;
        __syncthreads();
        s[t] += u;
        __syncthreads();
    }
    if (t < 196) g_bsum[t] = s[t] - v;
}

__global__ void k_scanC() {
    int i = blockIdx.x * 256 + threadIdx.x;
    if (i < NN) {
        int rs = g_rowstart[i] + g_bsum[blockIdx.x];
        g_rowstart[i] = rs;
        g_fillpos[i] = rs;
    }
    if (i == 0) g_rowstart[NN] = ETOTE;
}

__global__ void k_edge_fill(const int* __restrict__ ei) {
    int e = blockIdx.x * blockDim.x + threadIdx.x;
    if (e >= ETOTE) return;
    int src, dst;
    if (e < EE) { src = ei[e]; dst = ei[EE + e]; }
    else        { src = e - EE; dst = src; }
    int p = atomicAdd(&g_fillpos[dst], 1);
    g_csrsrc[p] = src;
}

// ---------------- GEMM: C[M,256] = A[M,K] @ W[K,256] ----------------
// 128x128 tile, 256 threads, 8x8 per thread, KT=8.
template<int K>
__global__ void __launch_bounds__(256, 2)
k_gemm(const float* __restrict__ A, const float* __restrict__ Wm) {
    __shared__ float As[8][132];     // transposed, padded
    __shared__ float Bs[8][128];
    float* __restrict__ Co = g_hl;
    const int M = NN;

    int tid = threadIdx.x;
    int m0 = blockIdx.x * 128;
    int n0 = blockIdx.y * 128;
    int tx = tid & 15, ty = tid >> 4;

    float acc[8][8];
    #pragma unroll
    for (int i = 0; i < 8; i++)
        #pragma unroll
        for (int j = 0; j < 8; j++) acc[i][j] = 0.f;

    // A-load indices: row r = tid>>1 (0..127), half = tid&1 (k offset 0/4)
    int ar = tid >> 1, ah = (tid & 1) * 4;
    // B-load: kk = tid>>5 (0..7), n = (tid&31)*4
    int bk = tid >> 5, bn = (tid & 31) * 4;

    for (int k0 = 0; k0 < K; k0 += 8) {
        {
            int gr = m0 + ar;
            float4 v = make_float4(0.f, 0.f, 0.f, 0.f);
            if (gr < M) v = *(const float4*)(A + (size_t)gr * K + k0 + ah);
            As[ah + 0][ar] = v.x; As[ah + 1][ar] = v.y;
            As[ah + 2][ar] = v.z; As[ah + 3][ar] = v.w;
        }
        {
            float4 v = *(const float4*)(Wm + (size_t)(k0 + bk) * HCC + n0 + bn);
            *(float4*)&Bs[bk][bn] = v;
        }
        __syncthreads();
        #pragma unroll
        for (int kk = 0; kk < 8; kk++) {
            float a[8], b[8];
            #pragma unroll
            for (int i = 0; i < 8; i++) a[i] = As[kk][ty * 8 + i];
            #pragma unroll
            for (int j = 0; j < 8; j++) b[j] = Bs[kk][tx * 8 + j];
            #pragma unroll
            for (int i = 0; i < 8; i++)
                #pragma unroll
                for (int j = 0; j < 8; j++) acc[i][j] += a[i] * b[j];
        }
        __syncthreads();
    }
    #pragma unroll
    for (int i = 0; i < 8; i++) {
        int gr = m0 + ty * 8 + i;
        if (gr < M) {
            float* orow = Co + (size_t)gr * HCC + n0 + tx * 8;
            *(float4*)(orow + 0) = make_float4(acc[i][0], acc[i][1], acc[i][2], acc[i][3]);
            *(float4*)(orow + 4) = make_float4(acc[i][4], acc[i][5], acc[i][6], acc[i][7]);
        }
    }
}

// ---------------- attention logits ----------------
__global__ void k_alpha(const float* __restrict__ asrc, const float* __restrict__ adst) {
    int gid = blockIdx.x * blockDim.x + threadIdx.x;
    int warp = gid >> 5;
    int lane = gid & 31;
    if (warp >= NN * HH) return;
    int n = warp >> 2;
    int h = warp & 3;
    const float* row = g_hl + (size_t)n * HCC + h * CCD;
    float v0 = row[lane], v1 = row[lane + 32];
    float s1 = v0 * asrc[h * CCD + lane] + v1 * asrc[h * CCD + lane + 32];
    float s2 = v0 * adst[h * CCD + lane] + v1 * adst[h * CCD + lane + 32];
    #pragma unroll
    for (int off = 16; off; off >>= 1) {
        s1 += __shfl_down_sync(0xFFFFFFFFu, s1, off);
        s2 += __shfl_down_sync(0xFFFFFFFFu, s2, off);
    }
    if (lane == 0) {
        g_as[n * HH + h] = s1;
        g_ad[n * HH + h] = s2;
    }
}

// ---------------- GAT gather: one warp per dst node ----------------
__global__ void k_gat_gather() {
    int gid = blockIdx.x * blockDim.x + threadIdx.x;
    int dst = gid >> 5;
    int lane = gid & 31;
    if (dst >= NN) return;
    int h = lane >> 3;
    float adh = g_ad[dst * HH + h];
    int beg = g_rowstart[dst], end = g_rowstart[dst + 1];

    float mx = -1e30f;
    for (int e = beg; e < end; e++) {
        int s = __ldg(&g_csrsrc[e]);
        float v = __ldg(&g_as[s * HH + h]) + adh;
        v = (v > 0.f) ? v : 0.2f * v;
        mx = fmaxf(mx, v);
    }
    float sum = 0.f;
    for (int e = beg; e < end; e++) {
        int s = __ldg(&g_csrsrc[e]);
        float v = __ldg(&g_as[s * HH + h]) + adh;
        v = (v > 0.f) ? v : 0.2f * v;
        sum += expf(v - mx);
    }
    float rs = 1.f / sum;

    float acc[8];
    #pragma unroll
    for (int k = 0; k < 8; k++) acc[k] = 0.f;

    int e = beg;
    for (; e + 1 < end; e += 2) {
        int s0 = __ldg(&g_csrsrc[e]);
        int s1 = __ldg(&g_csrsrc[e + 1]);
        float v0 = __ldg(&g_as[s0 * HH + h]) + adh;
        float v1 = __ldg(&g_as[s1 * HH + h]) + adh;
        v0 = (v0 > 0.f) ? v0 : 0.2f * v0;
        v1 = (v1 > 0.f) ? v1 : 0.2f * v1;
        float a0 = expf(v0 - mx) * rs;
        float a1 = expf(v1 - mx) * rs;
        const float4* hp0 = (const float4*)(g_hl + (size_t)s0 * HCC + lane * 8);
        const float4* hp1 = (const float4*)(g_hl + (size_t)s1 * HCC + lane * 8);
        float4 p0a = __ldg(hp0), p0b = __ldg(hp0 + 1);
        float4 p1a = __ldg(hp1), p1b = __ldg(hp1 + 1);
        acc[0] += a0 * p0a.x + a1 * p1a.x;
        acc[1] += a0 * p0a.y + a1 * p1a.y;
        acc[2] += a0 * p0a.z + a1 * p1a.z;
        acc[3] += a0 * p0a.w + a1 * p1a.w;
        acc[4] += a0 * p0b.x + a1 * p1b.x;
        acc[5] += a0 * p0b.y + a1 * p1b.y;
        acc[6] += a0 * p0b.z + a1 * p1b.z;
        acc[7] += a0 * p0b.w + a1 * p1b.w;
    }
    if (e < end) {
        int s0 = __ldg(&g_csrsrc[e]);
        float v0 = __ldg(&g_as[s0 * HH + h]) + adh;
        v0 = (v0 > 0.f) ? v0 : 0.2f * v0;
        float a0 = expf(v0 - mx) * rs;
        const float4* hp0 = (const float4*)(g_hl + (size_t)s0 * HCC + lane * 8);
        float4 p0a = __ldg(hp0), p0b = __ldg(hp0 + 1);
        acc[0] += a0 * p0a.x; acc[1] += a0 * p0a.y;
        acc[2] += a0 * p0a.z; acc[3] += a0 * p0a.w;
        acc[4] += a0 * p0b.x; acc[5] += a0 * p0b.y;
        acc[6] += a0 * p0b.z; acc[7] += a0 * p0b.w;
    }
    float4* op = (float4*)(g_hagg + (size_t)dst * HCC + lane * 8);
    op[0] = make_float4(acc[0], acc[1], acc[2], acc[3]);
    op[1] = make_float4(acc[4], acc[5], acc[6], acc[7]);
}

// ---------------- BatchNorm + ELU ----------------
__global__ void k_bn_zero() {
    int c = threadIdx.x;
    g_sum[c] = 0.0;
    g_sumsq[c] = 0.0;
    for (int i = c; i < BB * HCC; i += 256) g_pooled[i] = 0.f;
}

__global__ void k_bn_stats() {
    int c = threadIdx.x;
    int r0 = blockIdx.x * 200;
    float s = 0.f, sq = 0.f;
    for (int r = r0; r < r0 + 200; r++) {
        float v = g_hagg[(size_t)r * HCC + c];
        s += v;
        sq += v * v;
    }
    atomicAdd(&g_sum[c], (double)s);
    atomicAdd(&g_sumsq[c], (double)sq);
}

__global__ void k_bn_final() {
    int c = threadIdx.x;
    double m = g_sum[c] / (double)NN;
    double var = g_sumsq[c] / (double)NN - m * m;
    g_mean[c] = (float)m;
    g_rstd[c] = (float)(1.0 / sqrt(var + (double)BNEPS));
}

__global__ void k_bn_apply_elu(const float* __restrict__ gamma, const float* __restrict__ beta) {
    int idx = blockIdx.x * blockDim.x + threadIdx.x;
    if (idx >= NN * HCC / 4) return;
    int c0 = (idx * 4) & (HCC - 1);
    float4 v = ((float4*)g_hagg)[idx];
    float y;
    y = gamma[c0 + 0] * (v.x - g_mean[c0 + 0]) * g_rstd[c0 + 0] + beta[c0 + 0];
    v.x = (y > 0.f) ? y : expm1f(y);
    y = gamma[c0 + 1] * (v.y - g_mean[c0 + 1]) * g_rstd[c0 + 1] + beta[c0 + 1];
    v.y = (y > 0.f) ? y : expm1f(y);
    y = gamma[c0 + 2] * (v.z - g_mean[c0 + 2]) * g_rstd[c0 + 2] + beta[c0 + 2];
    v.z = (y > 0.f) ? y : expm1f(y);
    y = gamma[c0 + 3] * (v.w - g_mean[c0 + 3]) * g_rstd[c0 + 3] + beta[c0 + 3];
    v.w = (y > 0.f) ? y : expm1f(y);
    ((float4*)g_hagg)[idx] = v;
}

// ---------------- pooling + FC ----------------
__global__ void k_pool() {          // 4 partial blocks per graph
    int b = blockIdx.x >> 2;
    int part = blockIdx.x & 3;
    int c = threadIdx.x;
    int st = g_starts[b], cnt = g_counts[b];
    int per = (cnt + 3) >> 2;
    int r0 = st + part * per;
    int r1 = st + cnt; if (r0 + per < r1) r1 = r0 + per;
    float s = 0.f;
    for (int r = r0; r < r1; r++) s += g_hagg[(size_t)r * HCC + c];
    atomicAdd(&g_pooled[b * HCC + c], s);
}

__global__ void k_fc(const float* __restrict__ Wfc, const float* __restrict__ bfc,
                     float* __restrict__ out) {
    int b = blockIdx.x;
    int j = threadIdx.x;
    float scale = 1.f / (float)g_counts[b];
    float s = 0.f;
    #pragma unroll 4
    for (int k = 0; k < HCC; k++) s += g_pooled[b * HCC + k] * Wfc[k * OUTD + j];
    out[b * OUTD + j] = s * scale + bfc[j];
}

// ---------------- launch ----------------
extern "C" void kernel_launch(void* const* d_in, const int* in_sizes, int n_in,
                              void* d_out, int out_size) {
    const float* x      = (const float*)d_in[0];
    const int*   ei     = (const int*)d_in[1];
    const int*   batch  = (const int*)d_in[2];
    const float* Wpos   = (const float*)d_in[3];
    const float* bpos   = (const float*)d_in[4];
    const float* W1     = (const float*)d_in[5];
    const float* asrc1  = (const float*)d_in[6];
    const float* adst1  = (const float*)d_in[7];
    const float* gamma1 = (const float*)d_in[9];
    const float* beta1  = (const float*)d_in[10];
    const float* W2     = (const float*)d_in[11];
    const float* asrc2  = (const float*)d_in[12];
    const float* adst2  = (const float*)d_in[13];
    const float* gamma2 = (const float*)d_in[15];
    const float* beta2  = (const float*)d_in[16];
    const float* Wfc    = (const float*)d_in[17];
    const float* bfc    = (const float*)d_in[18];
    float* out = (float*)d_out;

    const int NB = (NN + 255) / 256;
    const int EB = (ETOTE + 255) / 256;

    k_prep_zero<<<NB, 256>>>();
    k_count_nodes<<<NB, 256>>>(batch);
    k_graph_meta<<<1, 64>>>();
    k_build_h0<<<(NN * (ENHD / 4) + 255) / 256, 256>>>(x, batch, Wpos, bpos);

    k_edge_count<<<EB, 256>>>(ei);
    k_scanA<<<NB, 256>>>();
    k_scanB<<<1, 256>>>();
    k_scanC<<<NB, 256>>>();
    k_edge_fill<<<EB, 256>>>(ei);

    dim3 ggrid((NN + 127) / 128, 2);

    // layer 1
    float* g_h0_p;  cudaGetSymbolAddress((void**)&g_h0_p,  g_h0);
    float* g_ag_p;  cudaGetSymbolAddress((void**)&g_ag_p,  g_hagg);
    k_gemm<ENHD><<<ggrid, 256>>>(g_h0_p, W1);
    k_alpha<<<(NN * HH * 32) / 256, 256>>>(asrc1, adst1);
    k_gat_gather<<<(NN * 32) / 256, 256>>>();
    k_bn_zero<<<1, 256>>>();
    k_bn_stats<<<250, 256>>>();
    k_bn_final<<<1, 256>>>();
    k_bn_apply_elu<<<(NN * HCC / 4) / 256, 256>>>(gamma1, beta1);

    // layer 2
    k_gemm<HCC><<<ggrid, 256>>>(g_ag_p, W2);
    k_alpha<<<(NN * HH * 32) / 256, 256>>>(asrc2, adst2);
    k_gat_gather<<<(NN * 32) / 256, 256>>>();
    k_bn_zero<<<1, 256>>>();
    k_bn_stats<<<250, 256>>>();
    k_bn_final<<<1, 256>>>();
    k_bn_apply_elu<<<(NN * HCC / 4) / 256, 256>>>(gamma2, beta2);

    k_pool<<<BB * 4, 256>>>();
    k_fc<<<BB, 128>>>(Wfc, bfc, out);
}

// round 5
// speedup vs baseline: 1.1598x; 1.0919x over previous
#include <cuda_runtime.h>
#include <cuda_bf16.h>
#include <cstdint>
#include <math.h>

#define NN    50000
#define EE    800000
#define ETOTE 850000
#define BB    64
#define FIN   128
#define POSD  16
#define ENHD  144
#define HH    4
#define CCD   64
#define HCC   256
#define OUTD  128
#define BNEPS 1e-5f

// ---------------- scratch ----------------
__device__ float  g_h0[NN * ENHD];
__device__ float  g_hl[NN * HCC];
__device__ float  g_hagg[NN * HCC];
__device__ __nv_bfloat16 g_abf[(NN + 256) * 768];   // [row][k'], padded rows stay zero
__device__ __nv_bfloat16 g_wbf[256 * 768];          // [n][k']
__device__ float  g_as[NN * HH];
__device__ float  g_ad[NN * HH];
__device__ int    g_counts[BB];
__device__ int    g_starts[BB];
__device__ int    g_gridsz[BB];
__device__ float  g_denomv[BB];
__device__ int    g_indeg[NN];
__device__ int    g_rowstart[NN + 1];
__device__ int    g_fillpos[NN];
__device__ int    g_csrsrc[ETOTE];
__device__ int    g_bsum[256];
__device__ double g_sum[HCC];
__device__ double g_sumsq[HCC];
__device__ float  g_mean[HCC];
__device__ float  g_rstd[HCC];
__device__ float  g_pooled[BB * HCC];

// ---------------- graph meta ----------------
__global__ void k_prep_zero() {
    int i = blockIdx.x * blockDim.x + threadIdx.x;
    if (i < NN) g_indeg[i] = 0;
    if (i < BB) g_counts[i] = 0;
}

__global__ void k_count_nodes(const int* __restrict__ batch) {
    int i = blockIdx.x * blockDim.x + threadIdx.x;
    if (i < NN) atomicAdd(&g_counts[batch[i]], 1);
}

__global__ void k_graph_meta() {
    int b = threadIdx.x;
    if (b >= BB) return;
    int st = 0;
    for (int j = 0; j < b; j++) st += g_counts[j];
    g_starts[b] = st;
    int c = g_counts[b];
    int g = (int)ceil(sqrt((double)c));
    g_gridsz[b] = g;
    int d = g - 1; if (d < 1) d = 1;
    g_denomv[b] = (float)d;
}

__global__ void k_build_h0(const float* __restrict__ x, const int* __restrict__ batch,
                           const float* __restrict__ Wpos, const float* __restrict__ bpos) {
    int tid = blockIdx.x * blockDim.x + threadIdx.x;
    if (tid >= NN * (ENHD / 4)) return;
    int n = tid / (ENHD / 4);
    int f4 = tid - n * (ENHD / 4);
    float4 v;
    if (f4 < FIN / 4) {
        v = ((const float4*)x)[(size_t)n * (FIN / 4) + f4];
    } else {
        int b = batch[n];
        int i = n - g_starts[b];
        int g = g_gridsz[b];
        float denom = g_denomv[b];
        int row = i / g;
        int col = i - row * g;
        float p0 = (float)row / denom;
        float p1 = (float)col / denom;
        int j = (f4 - FIN / 4) * 4;
        v.x = p0 * Wpos[j + 0] + p1 * Wpos[POSD + j + 0] + bpos[j + 0];
        v.y = p0 * Wpos[j + 1] + p1 * Wpos[POSD + j + 1] + bpos[j + 1];
        v.z = p0 * Wpos[j + 2] + p1 * Wpos[POSD + j + 2] + bpos[j + 2];
        v.w = p0 * Wpos[j + 3] + p1 * Wpos[POSD + j + 3] + bpos[j + 3];
    }
    ((float4*)g_h0)[tid] = v;
}

// ---------------- CSR by destination ----------------
__global__ void k_edge_count(const int* __restrict__ ei) {
    int e = blockIdx.x * blockDim.x + threadIdx.x;
    if (e >= ETOTE) return;
    int dst = (e < EE) ? ei[EE + e] : (e - EE);
    atomicAdd(&g_indeg[dst], 1);
}

__global__ void k_scanA() {
    __shared__ int s[256];
    int i = blockIdx.x * 256 + threadIdx.x;
    int v = (i < NN) ? g_indeg[i] : 0;
    s[threadIdx.x] = v;
    __syncthreads();
    for (int off = 1; off < 256; off <<= 1) {
        int t = (threadIdx.x >= off) ? s[threadIdx.x - off] : 0;
        __syncthreads();
        s[threadIdx.x] += t;
        __syncthreads();
    }
    if (i < NN) g_rowstart[i] = s[threadIdx.x] - v;
    if (threadIdx.x == 255) g_bsum[blockIdx.x] = s[255];
}

__global__ void k_scanB() {
    __shared__ int s[256];
    int t = threadIdx.x;
    int v = (t < 196) ? g_bsum[t] : 0;
    s[t] = v;
    __syncthreads();
    for (int off = 1; off < 256; off <<= 1) {
        int u = (t >= off) ? s[t - off] : 0;
        __syncthreads();
        s[t] += u;
        __syncthreads();
    }
    if (t < 196) g_bsum[t] = s[t] - v;
}

__global__ void k_scanC() {
    int i = blockIdx.x * 256 + threadIdx.x;
    if (i < NN) {
        int rs = g_rowstart[i] + g_bsum[blockIdx.x];
        g_rowstart[i] = rs;
        g_fillpos[i] = rs;
    }
    if (i == 0) g_rowstart[NN] = ETOTE;
}

__global__ void k_edge_fill(const int* __restrict__ ei) {
    int e = blockIdx.x * blockDim.x + threadIdx.x;
    if (e >= ETOTE) return;
    int src, dst;
    if (e < EE) { src = ei[e]; dst = ei[EE + e]; }
    else        { src = e - EE; dst = src; }
    int p = atomicAdd(&g_fillpos[dst], 1);
    g_csrsrc[p] = src;
}

// ---------------- bf16x3 split conversion ----------------
// A' = [A_hi | A_lo | A_hi] (K' = 3K)
__global__ void k_convA(const float* __restrict__ A, int K, int Kp) {
    int idx = blockIdx.x * blockDim.x + threadIdx.x;
    if (idx >= NN * K) return;
    int n = idx / K, k = idx - n * K;
    float x = A[idx];
    __nv_bfloat16 hi = __float2bfloat16(x);
    __nv_bfloat16 lo = __float2bfloat16(x - __bfloat162float(hi));
    size_t base = (size_t)n * Kp;
    g_abf[base + k] = hi;
    g_abf[base + K + k] = lo;
    g_abf[base + 2 * K + k] = hi;
}

// W' transposed to [n][k']: [W_hi | W_hi | W_lo], pad zero
__global__ void k_convW(const float* __restrict__ W, int K, int Kp) {
    int idx = blockIdx.x * blockDim.x + threadIdx.x;
    if (idx >= HCC * Kp) return;
    int n = idx / Kp, k = idx - n * Kp;
    __nv_bfloat16 v;
    if (k < K) {
        v = __float2bfloat16(W[(size_t)k * HCC + n]);
    } else if (k < 2 * K) {
        v = __float2bfloat16(W[(size_t)(k - K) * HCC + n]);
    } else if (k < 3 * K) {
        float x = W[(size_t)(k - 2 * K) * HCC + n];
        __nv_bfloat16 hi = __float2bfloat16(x);
        v = __float2bfloat16(x - __bfloat162float(hi));
    } else {
        v = __float2bfloat16(0.f);
    }
    g_wbf[idx] = v;
}

// ---------------- HMMA GEMM: g_hl[M,256] = A'[M,KP] @ W'^T  (W' is [n][k]) ----------------
// CTA = 128 rows x 128 cols, 8 warps (2 m x 4 n), warp = 64x32.
// mma.sync m16n8k16 bf16, K-chunk 32, double-buffered smem, pitch-40 rows.
template<int KP>
__global__ void __launch_bounds__(256) k_gemm_mma() {
    __shared__ __nv_bfloat16 As[2][128][40];
    __shared__ __nv_bfloat16 Bs[2][128][40];
    const int tid = threadIdx.x;
    const int lane = tid & 31, wid = tid >> 5;
    const int wm = wid & 1, wn = wid >> 1;
    const int g = lane >> 2, tq = lane & 3;
    const int m0 = blockIdx.x * 128, n0 = blockIdx.y * 128;

    float acc[4][4][4];
    #pragma unroll
    for (int a = 0; a < 4; a++)
        #pragma unroll
        for (int b = 0; b < 4; b++)
            #pragma unroll
            for (int c = 0; c < 4; c++) acc[a][b][c] = 0.f;

    const int lr = tid >> 2;        // 0..63
    const int lc = tid & 3;         // which 16B of the 64B k-chunk row
    const __nv_bfloat16* gA = g_abf + (size_t)m0 * KP;
    const __nv_bfloat16* gB = g_wbf + (size_t)n0 * KP;

    uint4 pa[2], pb[2];
    auto ld_chunk = [&](int k0) {
        #pragma unroll
        for (int i = 0; i < 2; i++) {
            int row = lr + i * 64;
            pa[i] = *(const uint4*)(gA + (size_t)row * KP + k0 + lc * 8);
            pb[i] = *(const uint4*)(gB + (size_t)row * KP + k0 + lc * 8);
        }
    };
    auto st_chunk = [&](int b) {
        #pragma unroll
        for (int i = 0; i < 2; i++) {
            int row = lr + i * 64;
            *(uint4*)&As[b][row][lc * 8] = pa[i];
            *(uint4*)&Bs[b][row][lc * 8] = pb[i];
        }
    };

    ld_chunk(0);
    st_chunk(0);
    __syncthreads();

    const int C = KP / 32;
    for (int c = 0; c < C; c++) {
        int cur = c & 1;
        if (c + 1 < C) ld_chunk((c + 1) * 32);
        #pragma unroll
        for (int ks = 0; ks < 2; ks++) {
            uint32_t af[4][4], bf[4][2];
            #pragma unroll
            for (int mt = 0; mt < 4; mt++) {
                int r = wm * 64 + mt * 16 + g;
                int cbase = ks * 16 + tq * 2;
                af[mt][0] = *(const uint32_t*)&As[cur][r][cbase];
                af[mt][1] = *(const uint32_t*)&As[cur][r + 8][cbase];
                af[mt][2] = *(const uint32_t*)&As[cur][r][cbase + 8];
                af[mt][3] = *(const uint32_t*)&As[cur][r + 8][cbase + 8];
            }
            #pragma unroll
            for (int nt = 0; nt < 4; nt++) {
                int r = wn * 32 + nt * 8 + g;
                int cbase = ks * 16 + tq * 2;
                bf[nt][0] = *(const uint32_t*)&Bs[cur][r][cbase];
                bf[nt][1] = *(const uint32_t*)&Bs[cur][r][cbase + 8];
            }
            #pragma unroll
            for (int mt = 0; mt < 4; mt++)
                #pragma unroll
                for (int nt = 0; nt < 4; nt++)
                    asm volatile(
                        "mma.sync.aligned.m16n8k16.row.col.f32.bf16.bf16.f32 "
                        "{%0,%1,%2,%3}, {%4,%5,%6,%7}, {%8,%9}, {%0,%1,%2,%3};\n"
                        : "+f"(acc[mt][nt][0]), "+f"(acc[mt][nt][1]),
                          "+f"(acc[mt][nt][2]), "+f"(acc[mt][nt][3])
                        : "r"(af[mt][0]), "r"(af[mt][1]), "r"(af[mt][2]), "r"(af[mt][3]),
                          "r"(bf[nt][0]), "r"(bf[nt][1]));
        }
        if (c + 1 < C) st_chunk(1 - cur);
        __syncthreads();
    }

    // epilogue: c0:(g,2tq) c1:(g,2tq+1) c2:(g+8,2tq) c3:(g+8,2tq+1)
    #pragma unroll
    for (int mt = 0; mt < 4; mt++) {
        int r0 = m0 + wm * 64 + mt * 16 + g;
        #pragma unroll
        for (int nt = 0; nt < 4; nt++) {
            int cc = n0 + wn * 32 + nt * 8 + tq * 2;
            if (r0 < NN)
                *(float2*)&g_hl[(size_t)r0 * HCC + cc] =
                    make_float2(acc[mt][nt][0], acc[mt][nt][1]);
            if (r0 + 8 < NN)
                *(float2*)&g_hl[(size_t)(r0 + 8) * HCC + cc] =
                    make_float2(acc[mt][nt][2], acc[mt][nt][3]);
        }
    }
}

// ---------------- attention logits ----------------
__global__ void k_alpha(const float* __restrict__ asrc, const float* __restrict__ adst) {
    int gid = blockIdx.x * blockDim.x + threadIdx.x;
    int warp = gid >> 5;
    int lane = gid & 31;
    if (warp >= NN * HH) return;
    int n = warp >> 2;
    int h = warp & 3;
    const float* row = g_hl + (size_t)n * HCC + h * CCD;
    float v0 = row[lane], v1 = row[lane + 32];
    float s1 = v0 * asrc[h * CCD + lane] + v1 * asrc[h * CCD + lane + 32];
    float s2 = v0 * adst[h * CCD + lane] + v1 * adst[h * CCD + lane + 32];
    #pragma unroll
    for (int off = 16; off; off >>= 1) {
        s1 += __shfl_down_sync(0xFFFFFFFFu, s1, off);
        s2 += __shfl_down_sync(0xFFFFFFFFu, s2, off);
    }
    if (lane == 0) {
        g_as[n * HH + h] = s1;
        g_ad[n * HH + h] = s2;
    }
}

// ---------------- GAT gather: one warp per dst node ----------------
__global__ void k_gat_gather() {
    int gid = blockIdx.x * blockDim.x + threadIdx.x;
    int dst = gid >> 5;
    int lane = gid & 31;
    if (dst >= NN) return;
    int h = lane >> 3;
    float adh = g_ad[dst * HH + h];
    int beg = g_rowstart[dst], end = g_rowstart[dst + 1];

    float mx = -1e30f;
    for (int e = beg; e < end; e++) {
        int s = __ldg(&g_csrsrc[e]);
        float v = __ldg(&g_as[s * HH + h]) + adh;
        v = (v > 0.f) ? v : 0.2f * v;
        mx = fmaxf(mx, v);
    }
    float sum = 0.f;
    for (int e = beg; e < end; e++) {
        int s = __ldg(&g_csrsrc[e]);
        float v = __ldg(&g_as[s * HH + h]) + adh;
        v = (v > 0.f) ? v : 0.2f * v;
        sum += expf(v - mx);
    }
    float rs = 1.f / sum;

    float acc[8];
    #pragma unroll
    for (int k = 0; k < 8; k++) acc[k] = 0.f;

    int e = beg;
    for (; e + 1 < end; e += 2) {
        int s0 = __ldg(&g_csrsrc[e]);
        int s1 = __ldg(&g_csrsrc[e + 1]);
        float v0 = __ldg(&g_as[s0 * HH + h]) + adh;
        float v1 = __ldg(&g_as[s1 * HH + h]) + adh;
        v0 = (v0 > 0.f) ? v0 : 0.2f * v0;
        v1 = (v1 > 0.f) ? v1 : 0.2f * v1;
        float a0 = expf(v0 - mx) * rs;
        float a1 = expf(v1 - mx) * rs;
        const float4* hp0 = (const float4*)(g_hl + (size_t)s0 * HCC + lane * 8);
        const float4* hp1 = (const float4*)(g_hl + (size_t)s1 * HCC + lane * 8);
        float4 p0a = __ldg(hp0), p0b = __ldg(hp0 + 1);
        float4 p1a = __ldg(hp1), p1b = __ldg(hp1 + 1);
        acc[0] += a0 * p0a.x + a1 * p1a.x;
        acc[1] += a0 * p0a.y + a1 * p1a.y;
        acc[2] += a0 * p0a.z + a1 * p1a.z;
        acc[3] += a0 * p0a.w + a1 * p1a.w;
        acc[4] += a0 * p0b.x + a1 * p1b.x;
        acc[5] += a0 * p0b.y + a1 * p1b.y;
        acc[6] += a0 * p0b.z + a1 * p1b.z;
        acc[7] += a0 * p0b.w + a1 * p1b.w;
    }
    if (e < end) {
        int s0 = __ldg(&g_csrsrc[e]);
        float v0 = __ldg(&g_as[s0 * HH + h]) + adh;
        v0 = (v0 > 0.f) ? v0 : 0.2f * v0;
        float a0 = expf(v0 - mx) * rs;
        const float4* hp0 = (const float4*)(g_hl + (size_t)s0 * HCC + lane * 8);
        float4 p0a = __ldg(hp0), p0b = __ldg(hp0 + 1);
        acc[0] += a0 * p0a.x; acc[1] += a0 * p0a.y;
        acc[2] += a0 * p0a.z; acc[3] += a0 * p0a.w;
        acc[4] += a0 * p0b.x; acc[5] += a0 * p0b.y;
        acc[6] += a0 * p0b.z; acc[7] += a0 * p0b.w;
    }
    float4* op = (float4*)(g_hagg + (size_t)dst * HCC + lane * 8);
    op[0] = make_float4(acc[0], acc[1], acc[2], acc[3]);
    op[1] = make_float4(acc[4], acc[5], acc[6], acc[7]);
}

// ---------------- BatchNorm + ELU ----------------
__global__ void k_bn_zero() {
    int c = threadIdx.x;
    g_sum[c] = 0.0;
    g_sumsq[c] = 0.0;
    for (int i = c; i < BB * HCC; i += 256) g_pooled[i] = 0.f;
}

__global__ void k_bn_stats() {
    int c = threadIdx.x;
    int r0 = blockIdx.x * 200;
    float s = 0.f, sq = 0.f;
    for (int r = r0; r < r0 + 200; r++) {
        float v = g_hagg[(size_t)r * HCC + c];
        s += v;
        sq += v * v;
    }
    atomicAdd(&g_sum[c], (double)s);
    atomicAdd(&g_sumsq[c], (double)sq);
}

__global__ void k_bn_final() {
    int c = threadIdx.x;
    double m = g_sum[c] / (double)NN;
    double var = g_sumsq[c] / (double)NN - m * m;
    g_mean[c] = (float)m;
    g_rstd[c] = (float)(1.0 / sqrt(var + (double)BNEPS));
}

__global__ void k_bn_apply_elu(const float* __restrict__ gamma, const float* __restrict__ beta) {
    int idx = blockIdx.x * blockDim.x + threadIdx.x;
    if (idx >= NN * HCC / 4) return;
    int c0 = (idx * 4) & (HCC - 1);
    float4 v = ((float4*)g_hagg)[idx];
    float y;
    y = gamma[c0 + 0] * (v.x - g_mean[c0 + 0]) * g_rstd[c0 + 0] + beta[c0 + 0];
    v.x = (y > 0.f) ? y : expm1f(y);
    y = gamma[c0 + 1] * (v.y - g_mean[c0 + 1]) * g_rstd[c0 + 1] + beta[c0 + 1];
    v.y = (y > 0.f) ? y : expm1f(y);
    y = gamma[c0 + 2] * (v.z - g_mean[c0 + 2]) * g_rstd[c0 + 2] + beta[c0 + 2];
    v.z = (y > 0.f) ? y : expm1f(y);
    y = gamma[c0 + 3] * (v.w - g_mean[c0 + 3]) * g_rstd[c0 + 3] + beta[c0 + 3];
    v.w = (y > 0.f) ? y : expm1f(y);
    ((float4*)g_hagg)[idx] = v;
}

// ---------------- pooling + FC ----------------
__global__ void k_pool() {
    int b = blockIdx.x >> 2;
    int part = blockIdx.x & 3;
    int c = threadIdx.x;
    int st = g_starts[b], cnt = g_counts[b];
    int per = (cnt + 3) >> 2;
    int r0 = st + part * per;
    int r1 = st + cnt; if (r0 + per < r1) r1 = r0 + per;
    float s = 0.f;
    for (int r = r0; r < r1; r++) s += g_hagg[(size_t)r * HCC + c];
    atomicAdd(&g_pooled[b * HCC + c], s);
}

__global__ void k_fc(const float* __restrict__ Wfc, const float* __restrict__ bfc,
                     float* __restrict__ out) {
    int b = blockIdx.x;
    int j = threadIdx.x;
    float scale = 1.f / (float)g_counts[b];
    float s = 0.f;
    #pragma unroll 4
    for (int k = 0; k < HCC; k++) s += g_pooled[b * HCC + k] * Wfc[k * OUTD + j];
    out[b * OUTD + j] = s * scale + bfc[j];
}

// ---------------- launch ----------------
extern "C" void kernel_launch(void* const* d_in, const int* in_sizes, int n_in,
                              void* d_out, int out_size) {
    const float* x      = (const float*)d_in[0];
    const int*   ei     = (const int*)d_in[1];
    const int*   batch  = (const int*)d_in[2];
    const float* Wpos   = (const float*)d_in[3];
    const float* bpos   = (const float*)d_in[4];
    const float* W1     = (const float*)d_in[5];
    const float* asrc1  = (const float*)d_in[6];
    const float* adst1  = (const float*)d_in[7];
    const float* gamma1 = (const float*)d_in[9];
    const float* beta1  = (const float*)d_in[10];
    const float* W2     = (const float*)d_in[11];
    const float* asrc2  = (const float*)d_in[12];
    const float* adst2  = (const float*)d_in[13];
    const float* gamma2 = (const float*)d_in[15];
    const float* beta2  = (const float*)d_in[16];
    const float* Wfc    = (const float*)d_in[17];
    const float* bfc    = (const float*)d_in[18];
    float* out = (float*)d_out;

    const int NB = (NN + 255) / 256;
    const int EB = (ETOTE + 255) / 256;

    float* g_h0_p;  cudaGetSymbolAddress((void**)&g_h0_p,  g_h0);
    float* g_ag_p;  cudaGetSymbolAddress((void**)&g_ag_p,  g_hagg);

    k_prep_zero<<<NB, 256>>>();
    k_count_nodes<<<NB, 256>>>(batch);
    k_graph_meta<<<1, 64>>>();
    k_build_h0<<<(NN * (ENHD / 4) + 255) / 256, 256>>>(x, batch, Wpos, bpos);

    k_edge_count<<<EB, 256>>>(ei);
    k_scanA<<<NB, 256>>>();
    k_scanB<<<1, 256>>>();
    k_scanC<<<NB, 256>>>();
    k_edge_fill<<<EB, 256>>>(ei);

    dim3 ggrid((NN + 127) / 128, 2);   // 391 x 2

    // layer 1
    k_convW<<<(HCC * 448 + 255) / 256, 256>>>(W1, ENHD, 448);
    k_convA<<<(NN * ENHD + 255) / 256, 256>>>(g_h0_p, ENHD, 448);
    k_gemm_mma<448><<<ggrid, 256>>>();
    k_alpha<<<(NN * HH * 32) / 256, 256>>>(asrc1, adst1);
    k_gat_gather<<<(NN * 32) / 256, 256>>>();
    k_bn_zero<<<1, 256>>>();
    k_bn_stats<<<250, 256>>>();
    k_bn_final<<<1, 256>>>();
    k_bn_apply_elu<<<(NN * HCC / 4) / 256, 256>>>(gamma1, beta1);

    // layer 2
    k_convW<<<(HCC * 768 + 255) / 256, 256>>>(W2, HCC, 768);
    k_convA<<<(NN * HCC + 255) / 256, 256>>>(g_ag_p, HCC, 768);
    k_gemm_mma<768><<<ggrid, 256>>>();
    k_alpha<<<(NN * HH * 32) / 256, 256>>>(asrc2, adst2);
    k_gat_gather<<<(NN * 32) / 256, 256>>>();
    k_bn_zero<<<1, 256>>>();
    k_bn_stats<<<250, 256>>>();
    k_bn_final<<<1, 256>>>();
    k_bn_apply_elu<<<(NN * HCC / 4) / 256, 256>>>(gamma2, beta2);

    k_pool<<<BB * 4, 256>>>();
    k_fc<<<BB, 128>>>(Wfc, bfc, out);
}

// round 6
// speedup vs baseline: 1.3473x; 1.1617x over previous
#include <cuda_runtime.h>
#include <cuda_bf16.h>
#include <cstdint>
#include <math.h>

#define NN    50000
#define EE    800000
#define ETOTE 850000
#define BB    64
#define FIN   128
#define POSD  16
#define ENHD  144
#define HH    4
#define CCD   64
#define HCC   256
#define OUTD  128
#define BNEPS 1e-5f

// ---------------- scratch ----------------
__device__ float  g_h0[NN * ENHD];
__device__ float  g_hl[NN * HCC];
__device__ float  g_hagg[NN * HCC];
__device__ __nv_bfloat16 g_abf[(NN + 256) * 768];   // [row][k'], padded rows stay zero
__device__ __nv_bfloat16 g_wbf[256 * 768];          // [n][k']
__device__ float  g_as[NN * HH];
__device__ float  g_ad[NN * HH];
__device__ int    g_counts[BB];
__device__ int    g_starts[BB];
__device__ int    g_gridsz[BB];
__device__ float  g_denomv[BB];
__device__ int    g_indeg[NN];
__device__ int    g_rowstart[NN + 1];
__device__ int    g_fillpos[NN];
__device__ int    g_csrsrc[ETOTE];
__device__ int    g_bsum[256];
__device__ double g_sum[HCC];
__device__ double g_sumsq[HCC];
__device__ float  g_mean[HCC];
__device__ float  g_rstd[HCC];
__device__ float  g_pooled[BB * HCC];

// ---------------- graph meta ----------------
__global__ void k_prep_zero() {
    int i = blockIdx.x * blockDim.x + threadIdx.x;
    if (i < NN) g_indeg[i] = 0;
    if (i < BB) g_counts[i] = 0;
    if (i < HCC) { g_sum[i] = 0.0; g_sumsq[i] = 0.0; }
    if (i < BB * HCC) g_pooled[i] = 0.f;
}

__global__ void k_count_nodes(const int* __restrict__ batch) {
    int i = blockIdx.x * blockDim.x + threadIdx.x;
    if (i < NN) atomicAdd(&g_counts[batch[i]], 1);
}

__global__ void k_graph_meta() {
    int b = threadIdx.x;
    if (b >= BB) return;
    int st = 0;
    for (int j = 0; j < b; j++) st += g_counts[j];
    g_starts[b] = st;
    int c = g_counts[b];
    int g = (int)ceil(sqrt((double)c));
    g_gridsz[b] = g;
    int d = g - 1; if (d < 1) d = 1;
    g_denomv[b] = (float)d;
}

__global__ void k_build_h0(const float* __restrict__ x, const int* __restrict__ batch,
                           const float* __restrict__ Wpos, const float* __restrict__ bpos) {
    int tid = blockIdx.x * blockDim.x + threadIdx.x;
    if (tid >= NN * (ENHD / 4)) return;
    int n = tid / (ENHD / 4);
    int f4 = tid - n * (ENHD / 4);
    float4 v;
    if (f4 < FIN / 4) {
        v = ((const float4*)x)[(size_t)n * (FIN / 4) + f4];
    } else {
        int b = batch[n];
        int i = n - g_starts[b];
        int g = g_gridsz[b];
        float denom = g_denomv[b];
        int row = i / g;
        int col = i - row * g;
        float p0 = (float)row / denom;
        float p1 = (float)col / denom;
        int j = (f4 - FIN / 4) * 4;
        v.x = p0 * Wpos[j + 0] + p1 * Wpos[POSD + j + 0] + bpos[j + 0];
        v.y = p0 * Wpos[j + 1] + p1 * Wpos[POSD + j + 1] + bpos[j + 1];
        v.z = p0 * Wpos[j + 2] + p1 * Wpos[POSD + j + 2] + bpos[j + 2];
        v.w = p0 * Wpos[j + 3] + p1 * Wpos[POSD + j + 3] + bpos[j + 3];
    }
    ((float4*)g_h0)[tid] = v;
}

// ---------------- CSR by destination ----------------
__global__ void k_edge_count(const int* __restrict__ ei) {
    int e = blockIdx.x * blockDim.x + threadIdx.x;
    if (e >= ETOTE) return;
    int dst = (e < EE) ? ei[EE + e] : (e - EE);
    atomicAdd(&g_indeg[dst], 1);
}

__global__ void k_scanA() {
    __shared__ int s[256];
    int i = blockIdx.x * 256 + threadIdx.x;
    int v = (i < NN) ? g_indeg[i] : 0;
    s[threadIdx.x] = v;
    __syncthreads();
    for (int off = 1; off < 256; off <<= 1) {
        int t = (threadIdx.x >= off) ? s[threadIdx.x - off] : 0;
        __syncthreads();
        s[threadIdx.x] += t;
        __syncthreads();
    }
    if (i < NN) g_rowstart[i] = s[threadIdx.x] - v;
    if (threadIdx.x == 255) g_bsum[blockIdx.x] = s[255];
}

__global__ void k_scanB() {
    __shared__ int s[256];
    int t = threadIdx.x;
    int v = (t < 196) ? g_bsum[t] : 0;
    s[t] = v;
    __syncthreads();
    for (int off = 1; off < 256; off <<= 1) {
        int u = (t >= off) ? s[t - off] : 0;
        __syncthreads();
        s[t] += u;
        __syncthreads();
    }
    if (t < 196) g_bsum[t] = s[t] - v;
}

__global__ void k_scanC() {
    int i = blockIdx.x * 256 + threadIdx.x;
    if (i < NN) {
        int rs = g_rowstart[i] + g_bsum[blockIdx.x];
        g_rowstart[i] = rs;
        g_fillpos[i] = rs;
    }
    if (i == 0) g_rowstart[NN] = ETOTE;
}

__global__ void k_edge_fill(const int* __restrict__ ei) {
    int e = blockIdx.x * blockDim.x + threadIdx.x;
    if (e >= ETOTE) return;
    int src, dst;
    if (e < EE) { src = ei[e]; dst = ei[EE + e]; }
    else        { src = e - EE; dst = src; }
    int p = atomicAdd(&g_fillpos[dst], 1);
    g_csrsrc[p] = src;
}

// ---------------- bf16x3 split conversion ----------------
// A' = [A_hi | A_lo | A_hi] (K' = 3K)
__global__ void k_convA(const float* __restrict__ A, int K, int Kp) {
    int idx = blockIdx.x * blockDim.x + threadIdx.x;
    if (idx >= NN * K) return;
    int n = idx / K, k = idx - n * K;
    float x = A[idx];
    __nv_bfloat16 hi = __float2bfloat16(x);
    __nv_bfloat16 lo = __float2bfloat16(x - __bfloat162float(hi));
    size_t base = (size_t)n * Kp;
    g_abf[base + k] = hi;
    g_abf[base + K + k] = lo;
    g_abf[base + 2 * K + k] = hi;
}

// layer-2 A conversion with fused BatchNorm + ELU (K = HCC = 256, Kp = 768)
__global__ void k_convA_bn(const float* __restrict__ gamma, const float* __restrict__ beta) {
    int idx = blockIdx.x * blockDim.x + threadIdx.x;
    if (idx >= NN * HCC) return;
    int n = idx >> 8, k = idx & 255;
    float v = g_hagg[idx];
    float y = gamma[k] * (v - g_mean[k]) * g_rstd[k] + beta[k];
    y = (y > 0.f) ? y : expm1f(y);
    __nv_bfloat16 hi = __float2bfloat16(y);
    __nv_bfloat16 lo = __float2bfloat16(y - __bfloat162float(hi));
    size_t base = (size_t)n * 768;
    g_abf[base + k] = hi;
    g_abf[base + 256 + k] = lo;
    g_abf[base + 512 + k] = hi;
}

// W' transposed to [n][k']: [W_hi | W_hi | W_lo], pad zero
__global__ void k_convW(const float* __restrict__ W, int K, int Kp) {
    int idx = blockIdx.x * blockDim.x + threadIdx.x;
    if (idx >= HCC * Kp) return;
    int n = idx / Kp, k = idx - n * Kp;
    __nv_bfloat16 v;
    if (k < K) {
        v = __float2bfloat16(W[(size_t)k * HCC + n]);
    } else if (k < 2 * K) {
        v = __float2bfloat16(W[(size_t)(k - K) * HCC + n]);
    } else if (k < 3 * K) {
        float x = W[(size_t)(k - 2 * K) * HCC + n];
        __nv_bfloat16 hi = __float2bfloat16(x);
        v = __float2bfloat16(x - __bfloat162float(hi));
    } else {
        v = __float2bfloat16(0.f);
    }
    g_wbf[idx] = v;
}

// ---------------- HMMA GEMM: g_hl[M,256] = A'[M,KP] @ W'^T ----------------
template<int KP>
__global__ void __launch_bounds__(256) k_gemm_mma() {
    __shared__ __nv_bfloat16 As[2][128][40];
    __shared__ __nv_bfloat16 Bs[2][128][40];
    const int tid = threadIdx.x;
    const int lane = tid & 31, wid = tid >> 5;
    const int wm = wid & 1, wn = wid >> 1;
    const int g = lane >> 2, tq = lane & 3;
    const int m0 = blockIdx.x * 128, n0 = blockIdx.y * 128;

    float acc[4][4][4];
    #pragma unroll
    for (int a = 0; a < 4; a++)
        #pragma unroll
        for (int b = 0; b < 4; b++)
            #pragma unroll
            for (int c = 0; c < 4; c++) acc[a][b][c] = 0.f;

    const int lr = tid >> 2;
    const int lc = tid & 3;
    const __nv_bfloat16* gA = g_abf + (size_t)m0 * KP;
    const __nv_bfloat16* gB = g_wbf + (size_t)n0 * KP;

    uint4 pa[2], pb[2];
    auto ld_chunk = [&](int k0) {
        #pragma unroll
        for (int i = 0; i < 2; i++) {
            int row = lr + i * 64;
            pa[i] = *(const uint4*)(gA + (size_t)row * KP + k0 + lc * 8);
            pb[i] = *(const uint4*)(gB + (size_t)row * KP + k0 + lc * 8);
        }
    };
    auto st_chunk = [&](int b) {
        #pragma unroll
        for (int i = 0; i < 2; i++) {
            int row = lr + i * 64;
            *(uint4*)&As[b][row][lc * 8] = pa[i];
            *(uint4*)&Bs[b][row][lc * 8] = pb[i];
        }
    };

    ld_chunk(0);
    st_chunk(0);
    __syncthreads();

    const int C = KP / 32;
    for (int c = 0; c < C; c++) {
        int cur = c & 1;
        if (c + 1 < C) ld_chunk((c + 1) * 32);
        #pragma unroll
        for (int ks = 0; ks < 2; ks++) {
            uint32_t af[4][4], bf[4][2];
            #pragma unroll
            for (int mt = 0; mt < 4; mt++) {
                int r = wm * 64 + mt * 16 + g;
                int cbase = ks * 16 + tq * 2;
                af[mt][0] = *(const uint32_t*)&As[cur][r][cbase];
                af[mt][1] = *(const uint32_t*)&As[cur][r + 8][cbase];
                af[mt][2] = *(const uint32_t*)&As[cur][r][cbase + 8];
                af[mt][3] = *(const uint32_t*)&As[cur][r + 8][cbase + 8];
            }
            #pragma unroll
            for (int nt = 0; nt < 4; nt++) {
                int r = wn * 32 + nt * 8 + g;
                int cbase = ks * 16 + tq * 2;
                bf[nt][0] = *(const uint32_t*)&Bs[cur][r][cbase];
                bf[nt][1] = *(const uint32_t*)&Bs[cur][r][cbase + 8];
            }
            #pragma unroll
            for (int mt = 0; mt < 4; mt++)
                #pragma unroll
                for (int nt = 0; nt < 4; nt++)
                    asm volatile(
                        "mma.sync.aligned.m16n8k16.row.col.f32.bf16.bf16.f32 "
                        "{%0,%1,%2,%3}, {%4,%5,%6,%7}, {%8,%9}, {%0,%1,%2,%3};\n"
                        : "+f"(acc[mt][nt][0]), "+f"(acc[mt][nt][1]),
                          "+f"(acc[mt][nt][2]), "+f"(acc[mt][nt][3])
                        : "r"(af[mt][0]), "r"(af[mt][1]), "r"(af[mt][2]), "r"(af[mt][3]),
                          "r"(bf[nt][0]), "r"(bf[nt][1]));
        }
        if (c + 1 < C) st_chunk(1 - cur);
        __syncthreads();
    }

    #pragma unroll
    for (int mt = 0; mt < 4; mt++) {
        int r0 = m0 + wm * 64 + mt * 16 + g;
        #pragma unroll
        for (int nt = 0; nt < 4; nt++) {
            int cc = n0 + wn * 32 + nt * 8 + tq * 2;
            if (r0 < NN)
                *(float2*)&g_hl[(size_t)r0 * HCC + cc] =
                    make_float2(acc[mt][nt][0], acc[mt][nt][1]);
            if (r0 + 8 < NN)
                *(float2*)&g_hl[(size_t)(r0 + 8) * HCC + cc] =
                    make_float2(acc[mt][nt][2], acc[mt][nt][3]);
        }
    }
}

// ---------------- attention logits ----------------
__global__ void k_alpha(const float* __restrict__ asrc, const float* __restrict__ adst) {
    int gid = blockIdx.x * blockDim.x + threadIdx.x;
    int warp = gid >> 5;
    int lane = gid & 31;
    if (warp >= NN * HH) return;
    int n = warp >> 2;
    int h = warp & 3;
    const float* row = g_hl + (size_t)n * HCC + h * CCD;
    float v0 = row[lane], v1 = row[lane + 32];
    float s1 = v0 * asrc[h * CCD + lane] + v1 * asrc[h * CCD + lane + 32];
    float s2 = v0 * adst[h * CCD + lane] + v1 * adst[h * CCD + lane + 32];
    #pragma unroll
    for (int off = 16; off; off >>= 1) {
        s1 += __shfl_down_sync(0xFFFFFFFFu, s1, off);
        s2 += __shfl_down_sync(0xFFFFFFFFu, s2, off);
    }
    if (lane == 0) {
        g_as[n * HH + h] = s1;
        g_ad[n * HH + h] = s2;
    }
}

// ---------------- GAT gather: single pass (no max-shift; logits are O(1)) ----------------
__global__ void k_gat_gather() {
    int gid = blockIdx.x * blockDim.x + threadIdx.x;
    int dst = gid >> 5;
    int lane = gid & 31;
    if (dst >= NN) return;
    int h = lane >> 3;
    float adh = g_ad[dst * HH + h];
    int beg = g_rowstart[dst], end = g_rowstart[dst + 1];

    float sum = 0.f;
    float acc[8];
    #pragma unroll
    for (int k = 0; k < 8; k++) acc[k] = 0.f;

    int e = beg;
    for (; e + 1 < end; e += 2) {
        int s0 = __ldg(&g_csrsrc[e]);
        int s1 = __ldg(&g_csrsrc[e + 1]);
        float v0 = __ldg(&g_as[s0 * HH + h]) + adh;
        float v1 = __ldg(&g_as[s1 * HH + h]) + adh;
        v0 = (v0 > 0.f) ? v0 : 0.2f * v0;
        v1 = (v1 > 0.f) ? v1 : 0.2f * v1;
        float w0 = expf(v0);
        float w1 = expf(v1);
        sum += w0 + w1;
        const float4* hp0 = (const float4*)(g_hl + (size_t)s0 * HCC + lane * 8);
        const float4* hp1 = (const float4*)(g_hl + (size_t)s1 * HCC + lane * 8);
        float4 p0a = __ldg(hp0), p0b = __ldg(hp0 + 1);
        float4 p1a = __ldg(hp1), p1b = __ldg(hp1 + 1);
        acc[0] += w0 * p0a.x + w1 * p1a.x;
        acc[1] += w0 * p0a.y + w1 * p1a.y;
        acc[2] += w0 * p0a.z + w1 * p1a.z;
        acc[3] += w0 * p0a.w + w1 * p1a.w;
        acc[4] += w0 * p0b.x + w1 * p1b.x;
        acc[5] += w0 * p0b.y + w1 * p1b.y;
        acc[6] += w0 * p0b.z + w1 * p1b.z;
        acc[7] += w0 * p0b.w + w1 * p1b.w;
    }
    if (e < end) {
        int s0 = __ldg(&g_csrsrc[e]);
        float v0 = __ldg(&g_as[s0 * HH + h]) + adh;
        v0 = (v0 > 0.f) ? v0 : 0.2f * v0;
        float w0 = expf(v0);
        sum += w0;
        const float4* hp0 = (const float4*)(g_hl + (size_t)s0 * HCC + lane * 8);
        float4 p0a = __ldg(hp0), p0b = __ldg(hp0 + 1);
        acc[0] += w0 * p0a.x; acc[1] += w0 * p0a.y;
        acc[2] += w0 * p0a.z; acc[3] += w0 * p0a.w;
        acc[4] += w0 * p0b.x; acc[5] += w0 * p0b.y;
        acc[6] += w0 * p0b.z; acc[7] += w0 * p0b.w;
    }
    float rs = 1.f / sum;
    float4* op = (float4*)(g_hagg + (size_t)dst * HCC + lane * 8);
    op[0] = make_float4(acc[0] * rs, acc[1] * rs, acc[2] * rs, acc[3] * rs);
    op[1] = make_float4(acc[4] * rs, acc[5] * rs, acc[6] * rs, acc[7] * rs);
}

// ---------------- BatchNorm stats ----------------
__global__ void k_bn_stats() {
    int c = threadIdx.x;
    int r0 = blockIdx.x * 200;
    float s = 0.f, sq = 0.f;
    for (int r = r0; r < r0 + 200; r++) {
        float v = g_hagg[(size_t)r * HCC + c];
        s += v;
        sq += v * v;
    }
    atomicAdd(&g_sum[c], (double)s);
    atomicAdd(&g_sumsq[c], (double)sq);
}

__global__ void k_bn_final() {
    int c = threadIdx.x;
    double m = g_sum[c] / (double)NN;
    double var = g_sumsq[c] / (double)NN - m * m;
    g_mean[c] = (float)m;
    g_rstd[c] = (float)(1.0 / sqrt(var + (double)BNEPS));
    g_sum[c] = 0.0;          // reset for next layer's stats
    g_sumsq[c] = 0.0;
}

// ---------------- pooling (fused layer-2 BN + ELU) + FC ----------------
__global__ void k_pool(const float* __restrict__ gamma, const float* __restrict__ beta) {
    int b = blockIdx.x >> 2;
    int part = blockIdx.x & 3;
    int c = threadIdx.x;
    float ga = gamma[c], be = beta[c], m = g_mean[c], r_ = g_rstd[c];
    int st = g_starts[b], cnt = g_counts[b];
    int per = (cnt + 3) >> 2;
    int r0 = st + part * per;
    int r1 = st + cnt; if (r0 + per < r1) r1 = r0 + per;
    float s = 0.f;
    for (int r = r0; r < r1; r++) {
        float v = g_hagg[(size_t)r * HCC + c];
        float y = ga * (v - m) * r_ + be;
        s += (y > 0.f) ? y : expm1f(y);
    }
    atomicAdd(&g_pooled[b * HCC + c], s);
}

__global__ void k_fc(const float* __restrict__ Wfc, const float* __restrict__ bfc,
                     float* __restrict__ out) {
    int b = blockIdx.x;
    int j = threadIdx.x;
    float scale = 1.f / (float)g_counts[b];
    float s = 0.f;
    #pragma unroll 4
    for (int k = 0; k < HCC; k++) s += g_pooled[b * HCC + k] * Wfc[k * OUTD + j];
    out[b * OUTD + j] = s * scale + bfc[j];
}

// ---------------- launch ----------------
extern "C" void kernel_launch(void* const* d_in, const int* in_sizes, int n_in,
                              void* d_out, int out_size) {
    const float* x      = (const float*)d_in[0];
    const int*   ei     = (const int*)d_in[1];
    const int*   batch  = (const int*)d_in[2];
    const float* Wpos   = (const float*)d_in[3];
    const float* bpos   = (const float*)d_in[4];
    const float* W1     = (const float*)d_in[5];
    const float* asrc1  = (const float*)d_in[6];
    const float* adst1  = (const float*)d_in[7];
    const float* gamma1 = (const float*)d_in[9];
    const float* beta1  = (const float*)d_in[10];
    const float* W2     = (const float*)d_in[11];
    const float* asrc2  = (const float*)d_in[12];
    const float* adst2  = (const float*)d_in[13];
    const float* gamma2 = (const float*)d_in[15];
    const float* beta2  = (const float*)d_in[16];
    const float* Wfc    = (const float*)d_in[17];
    const float* bfc    = (const float*)d_in[18];
    float* out = (float*)d_out;

    const int NB = (NN + 255) / 256;
    const int EB = (ETOTE + 255) / 256;

    float* g_h0_p;  cudaGetSymbolAddress((void**)&g_h0_p,  g_h0);

    k_prep_zero<<<NB, 256>>>();
    k_count_nodes<<<NB, 256>>>(batch);
    k_graph_meta<<<1, 64>>>();
    k_build_h0<<<(NN * (ENHD / 4) + 255) / 256, 256>>>(x, batch, Wpos, bpos);

    k_edge_count<<<EB, 256>>>(ei);
    k_scanA<<<NB, 256>>>();
    k_scanB<<<1, 256>>>();
    k_scanC<<<NB, 256>>>();
    k_edge_fill<<<EB, 256>>>(ei);

    dim3 ggrid((NN + 127) / 128, 2);

    // layer 1
    k_convW<<<(HCC * 448 + 255) / 256, 256>>>(W1, ENHD, 448);
    k_convA<<<(NN * ENHD + 255) / 256, 256>>>(g_h0_p, ENHD, 448);
    k_gemm_mma<448><<<ggrid, 256>>>();
    k_alpha<<<(NN * HH * 32) / 256, 256>>>(asrc1, adst1);
    k_gat_gather<<<(NN * 32) / 256, 256>>>();
    k_bn_stats<<<250, 256>>>();
    k_bn_final<<<1, 256>>>();

    // layer 2 (BN1+ELU fused into convA_bn)
    k_convW<<<(HCC * 768 + 255) / 256, 256>>>(W2, HCC, 768);
    k_convA_bn<<<(NN * HCC + 255) / 256, 256>>>(gamma1, beta1);
    k_gemm_mma<768><<<ggrid, 256>>>();
    k_alpha<<<(NN * HH * 32) / 256, 256>>>(asrc2, adst2);
    k_gat_gather<<<(NN * 32) / 256, 256>>>();
    k_bn_stats<<<250, 256>>>();
    k_bn_final<<<1, 256>>>();

    // pool (BN2+ELU fused) + fc
    k_pool<<<BB * 4, 256>>>(gamma2, beta2);
    k_fc<<<BB, 128>>>(Wfc, bfc, out);
}